// round 8
// baseline (speedup 1.0000x reference)
#include <cuda_runtime.h>
#include <cuda_bf16.h>
#include <cstdint>

#define TT 512
#define BATCH 128
#define IND 128
#define HH 1024
#define OUTD 64
#define NCTA 130
#define NTHR 512
#define KCH 32
#define NCHW 18                     // chunks per warp (parity-split halves of 36)
#define NKS 72                      // 1152 / 16 k-steps

#define OFF_BIAS 0
#define OFF_ABUF 1024
#define WSLOT 4096                  // per-warp: 2 stages x (hi 1KB + lo 1KB)
#define OFF_BFRAG (OFF_ABUF + 16 * WSLOT)       // 66560
#define BFRAG_SZ (NKS * 4 * 32 * 16)            // 147456 (hi+lo interleaved)
#define SMEM_TOTAL (OFF_BFRAG + BFRAG_SZ)       // 214016

__device__ __align__(16) __nv_bfloat16 g_u_hi[(size_t)TT * BATCH * IND];
__device__ __align__(16) __nv_bfloat16 g_u_lo[(size_t)TT * BATCH * IND];
__device__ __align__(16) __nv_bfloat16 g_h_hi[2][BATCH * HH];
__device__ __align__(16) __nv_bfloat16 g_h_lo[2][BATCH * HH];
__device__ unsigned int g_bar_count = 0;
__device__ unsigned int g_bar_gen = 0;

__device__ __forceinline__ float sg(float x) { return __fdividef(1.0f, 1.0f + __expf(-x)); }
__device__ __forceinline__ float th(float x) { return __fdividef(2.0f, 1.0f + __expf(-2.0f * x)) - 1.0f; }

__device__ __forceinline__ uint32_t pkbf(float a, float b, uint32_t& lo) {
    __nv_bfloat16 ah = __float2bfloat16_rn(a), bh = __float2bfloat16_rn(b);
    __nv_bfloat16 al = __float2bfloat16_rn(a - __bfloat162float(ah));
    __nv_bfloat16 bl = __float2bfloat16_rn(b - __bfloat162float(bh));
    lo = (uint32_t)__bfloat16_as_ushort(al) | ((uint32_t)__bfloat16_as_ushort(bl) << 16);
    return (uint32_t)__bfloat16_as_ushort(ah) | ((uint32_t)__bfloat16_as_ushort(bh) << 16);
}

__device__ __forceinline__ uint32_t smem_u32(const void* p) {
    uint32_t a;
    asm("{ .reg .u64 t; cvta.to.shared.u64 t, %1; cvt.u32.u64 %0, t; }" : "=r"(a) : "l"(p));
    return a;
}

__device__ __forceinline__ void ldsm_x4(uint32_t* r, uint32_t addr) {
    asm volatile("ldmatrix.sync.aligned.m8n8.x4.shared.b16 {%0,%1,%2,%3}, [%4];"
        : "=r"(r[0]), "=r"(r[1]), "=r"(r[2]), "=r"(r[3]) : "r"(addr));
}

__device__ __forceinline__ void mma_bf16(float* d, const uint32_t* a, uint32_t b0, uint32_t b1) {
    asm volatile(
        "mma.sync.aligned.m16n8k16.row.col.f32.bf16.bf16.f32 "
        "{%0,%1,%2,%3}, {%4,%5,%6,%7}, {%8,%9}, {%0,%1,%2,%3};"
        : "+f"(d[0]), "+f"(d[1]), "+f"(d[2]), "+f"(d[3])
        : "r"(a[0]), "r"(a[1]), "r"(a[2]), "r"(a[3]), "r"(b0), "r"(b1));
}

#define PAIR_BAR(id) asm volatile("bar.sync %0, %1;" :: "r"(id), "r"(64) : "memory")

__device__ __forceinline__ void grid_barrier_full(unsigned int& epoch) {
    __syncthreads();
    if (threadIdx.x == 0) {
        __threadfence();
        unsigned int target = epoch + 1;
        unsigned int arr = atomicAdd(&g_bar_count, 1u);
        if (arr == NCTA - 1) {
            atomicExch(&g_bar_count, 0u);
            __threadfence();
            atomicAdd(&g_bar_gen, 1u);
        } else {
            while ((int)(*(volatile unsigned int*)&g_bar_gen - target) < 0) __nanosleep(32);
        }
        epoch = target;
        __threadfence();
    }
    __syncthreads();
}

__device__ __forceinline__ void bar_arrive() {
    if (threadIdx.x == 0) {
        __threadfence();
        unsigned int arr = atomicAdd(&g_bar_count, 1u);
        if (arr == NCTA - 1) {
            atomicExch(&g_bar_count, 0u);
            __threadfence();
            atomicAdd(&g_bar_gen, 1u);
        }
    }
}
__device__ __forceinline__ void bar_wait(unsigned int target) {
    while ((int)(*(volatile unsigned int*)&g_bar_gen - target) < 0) { }
    __threadfence();
}

// per-warp chunk load: warp's 16 rows x 32 k, hi+lo -> 2+2 uint4 regs.
// tu = u timestep (chunks 0..3); hphase = h buffer (chunks >= 4). Distinct
// on the drain step t=TT (tu clamped, hphase = t&1).
__device__ __forceinline__ void load_chunk_w(int tu, int hphase, int c,
    int rowbase, int lane, uint4* vhi, uint4* vlo)
{
    const __nv_bfloat16 *srcH, *srcL;
    int rstride;
    if (c < 4) {
        size_t base = (size_t)tu * BATCH * IND + c * KCH;
        srcH = g_u_hi + base; srcL = g_u_lo + base; rstride = IND;
    } else {
        size_t base = (size_t)c * KCH - IND;
        srcH = g_h_hi[hphase] + base; srcL = g_h_lo[hphase] + base; rstride = HH;
    }
    const int o = lane & 3;
    const int rb = rowbase + (lane >> 2);
    #pragma unroll
    for (int i = 0; i < 2; ++i) {
        int row = rb + 8 * i;
        vhi[i] = __ldcg((const uint4*)(srcH + (size_t)row * rstride + o * 8));
        vlo[i] = __ldcg((const uint4*)(srcL + (size_t)row * rstride + o * 8));
    }
}

__global__ void __launch_bounds__(NTHR, 1)
lstm_mma(const float* __restrict__ u, const float* __restrict__ x0,
         const float* __restrict__ kfiz, const float* __restrict__ bfiz,
         const float* __restrict__ kr, const float* __restrict__ br,
         const float* __restrict__ wout, const float* __restrict__ bout,
         float* __restrict__ y)
{
    extern __shared__ char smem[];
    const int tid = threadIdx.x;
    const int bid = blockIdx.x;
    const int warp = tid >> 5, lane = tid & 31;
    const int mg = warp >> 1, kh = warp & 1;
    const int rowbase = mg * 16;
    const int gid = lane >> 2, tig = lane & 3;
    const uint32_t sb = smem_u32(smem);
    float* bias_s = (float*)(smem + OFF_BIAS);
    unsigned int* base_s = (unsigned int*)(smem + OFF_BIAS + 512);

    // ---- init: weights -> smem B fragments (hi/lo interleaved uint4) ----
    for (int idx = tid; idx < NKS * 4 * 32; idx += NTHR) {
        int l = idx & 31;
        int nt = (idx >> 5) & 3;
        int s = idx >> 7;
        int nloc = nt * 8 + (l >> 2);
        int k0 = s * 16 + (l & 3) * 2;
        float w[4];
        #pragma unroll
        for (int q = 0; q < 4; ++q) {
            int k = k0 + (q >> 1) * 8 + (q & 1);
            float v;
            if (bid < 128) {
                int g = nloc >> 3, hid = bid * 8 + (nloc & 7);
                v = (g < 3) ? kfiz[(size_t)k * 3072 + g * 1024 + hid]
                            : kr[(size_t)k * 1024 + hid];
            } else {
                int col = (bid - 128) * 32 + nloc;
                v = (k < IND) ? 0.0f : wout[(size_t)(k - IND) * OUTD + col];
            }
            w[q] = v;
        }
        uint32_t lo0, lo1;
        uint32_t h0 = pkbf(w[0], w[1], lo0);
        uint32_t h1 = pkbf(w[2], w[3], lo1);
        *(uint4*)(smem + OFF_BFRAG + (uint32_t)idx * 16) = make_uint4(h0, h1, lo0, lo1);
    }
    if (tid < 32) {
        float bv;
        if (bid < 128) {
            int g = tid >> 3, hid = bid * 8 + (tid & 7);
            bv = (g < 3) ? bfiz[g * 1024 + hid] : br[hid];
        } else bv = bout[(bid - 128) * 32 + tid];
        bias_s[tid] = bv;
    }

    // ---- init: u -> (t,b,k) bf16 hi/lo, grid-strided ----
    {
        const size_t UN = (size_t)TT * BATCH * IND;
        for (size_t i = (size_t)bid * NTHR + tid; i < UN; i += (size_t)NCTA * NTHR) {
            int b = (int)(i / (TT * IND));
            int rem = (int)(i % (TT * IND));
            float w = u[i];
            __nv_bfloat16 hi = __float2bfloat16_rn(w);
            size_t o = ((size_t)(rem / IND) * BATCH + b) * IND + (rem % IND);
            g_u_hi[o] = hi;
            g_u_lo[o] = __float2bfloat16_rn(w - __bfloat162float(hi));
        }
    }

    // ---- init: c0 (kh==0 warps own the epilogue), h0 -> g_h[0] ----
    float creg[4];
    if (bid < 128) {
        if (kh == 0) {
            #pragma unroll
            for (int q = 0; q < 4; ++q) {
                int row = rowbase + gid + (q >> 1) * 8;
                creg[q] = x0[(size_t)row * 2 * HH + HH + bid * 8 + tig * 2 + (q & 1)];
            }
        }
        if (tid < 128) {
            const float* xp = x0 + (size_t)tid * 2 * HH;
            uint32_t hh[4], ll[4];
            #pragma unroll
            for (int q = 0; q < 4; ++q)
                hh[q] = pkbf(xp[bid * 8 + 2 * q], xp[bid * 8 + 2 * q + 1], ll[q]);
            size_t ho = (size_t)tid * HH + bid * 8;
            __stcg((uint4*)(g_h_hi[0] + ho), make_uint4(hh[0], hh[1], hh[2], hh[3]));
            __stcg((uint4*)(g_h_lo[0] + ho), make_uint4(ll[0], ll[1], ll[2], ll[3]));
        }
    }

    unsigned int epoch = 0;
    if (tid == 0) epoch = *(volatile unsigned int*)&g_bar_gen;
    grid_barrier_full(epoch);
    if (tid == 0) *base_s = epoch;
    __syncthreads();
    const unsigned int base = *base_s;

    float bcol[4][2];
    #pragma unroll
    for (int nt = 0; nt < 4; ++nt) {
        bcol[nt][0] = bias_s[nt * 8 + tig * 2];
        bcol[nt][1] = bias_s[nt * 8 + tig * 2 + 1];
    }

    // ldsm addressing in 16x64B tile (SW64 per-row XOR)
    uint32_t amo, axc;
    const int ach = lane >> 4;           // 16B col-half within kstep
    {
        int rloc = (lane & 7) + ((lane >> 3) & 1) * 8;
        amo = (uint32_t)rloc * 64;
        axc = ((uint32_t)rloc * 8) & 0x30;
    }
    // store offsets (per lane, swizzled): 16 rows x 64B, 2 uint4/lane
    uint32_t soff[2];
    {
        int o = lane & 3;
        #pragma unroll
        for (int i = 0; i < 2; ++i) {
            uint32_t row = (uint32_t)(lane >> 2) + 8 * i;
            soff[i] = row * 64 + (((uint32_t)o * 16) ^ ((row * 8) & 0x30));
        }
    }

    const char* bf = smem + OFF_BFRAG;
    const uint32_t slot0 = sb + OFF_ABUF + warp * WSLOT;
    char* slotp = smem + OFF_ABUF + warp * WSLOT;
    char* pair0 = smem + OFF_ABUF + (warp & ~1) * WSLOT;   // kh0 slot of pair
    const int barid = 1 + mg;

    uint4 vhi[2], vlo[2];
    load_chunk_w(0, 0, kh, rowbase, lane, vhi, vlo);

    for (int t = 0; t <= TT; ++t) {
        const int tt = (t < TT) ? t : (TT - 1);   // u timestep (clamped)
        const int hp = t & 1;                     // h buffer phase (NOT clamped)

        float acc[4][4];
        #pragma unroll
        for (int nt = 0; nt < 4; ++nt)
            #pragma unroll
            for (int q = 0; q < 4; ++q) acc[nt][q] = 0.0f;

        for (int lc = 0; lc < NCHW; ++lc) {
            const uint32_t stg = (uint32_t)(lc & 1) * 2048;
            char* sp = slotp + stg;
            #pragma unroll
            for (int i = 0; i < 2; ++i) {
                *(uint4*)(sp + soff[i]) = vhi[i];
                *(uint4*)(sp + 1024 + soff[i]) = vlo[i];
            }
            __syncwarp();

            if (lc + 1 < NCHW) {
                if (lc + 1 == 2) bar_wait(base + t);   // h(t) published
                load_chunk_w(tt, hp, 2 * (lc + 1) + kh, rowbase, lane, vhi, vlo);
            } else if (t < TT) {
                int tn = (t + 1 < TT) ? (t + 1) : (TT - 1);
                load_chunk_w(tn, 0, kh, rowbase, lane, vhi, vlo);   // u chunk
            }

            const uint32_t sbase = slot0 + stg;
            #pragma unroll
            for (int kk = 0; kk < 2; ++kk) {
                uint32_t aa = sbase + amo + ((((uint32_t)(kk * 2 + ach)) * 16) ^ axc);
                uint32_t ah[4], al[4];
                ldsm_x4(ah, aa);
                ldsm_x4(al, aa + 1024);
                int s = 4 * lc + 2 * kh + kk;
                #pragma unroll
                for (int nt = 0; nt < 4; ++nt) {
                    uint4 bb = *(const uint4*)(bf + (uint32_t)((s * 4 + nt) * 32 + lane) * 16);
                    mma_bf16(acc[nt], ah, bb.x, bb.y);
                    mma_bf16(acc[nt], ah, bb.z, bb.w);
                    mma_bf16(acc[nt], al, bb.x, bb.y);
                }
            }
        }

        // ---- pair reduction via named barriers (pairs stay independent) ----
        PAIR_BAR(barid);                 // kh0's last ldsm done before overwrite
        if (kh == 1) {
            #pragma unroll
            for (int nt = 0; nt < 4; ++nt)
                *(float4*)(pair0 + (uint32_t)nt * 512 + lane * 16) =
                    make_float4(acc[nt][0], acc[nt][1], acc[nt][2], acc[nt][3]);
        }
        PAIR_BAR(barid);

        if (kh == 0) {
            #pragma unroll
            for (int nt = 0; nt < 4; ++nt) {
                float4 p = *(const float4*)(pair0 + (uint32_t)nt * 512 + lane * 16);
                acc[nt][0] += p.x; acc[nt][1] += p.y;
                acc[nt][2] += p.z; acc[nt][3] += p.w;
            }
            if (bid < 128) {
                if (t < TT) {
                    float hv[4];
                    #pragma unroll
                    for (int q = 0; q < 4; ++q) {
                        int e = q & 1;
                        float fp = acc[0][q] + bcol[0][e];
                        float ip = acc[1][q] + bcol[1][e];
                        float zp = acc[2][q] + bcol[2][e];
                        float rp = acc[3][q] + bcol[3][e];
                        creg[q] = sg(fp) * creg[q] + sg(ip) * th(rp);
                        hv[q] = sg(zp) * th(creg[q]);
                    }
                    int p = (t + 1) & 1;
                    #pragma unroll
                    for (int qp = 0; qp < 2; ++qp) {
                        int row = rowbase + gid + qp * 8;
                        uint32_t lo;
                        uint32_t hi = pkbf(hv[qp * 2], hv[qp * 2 + 1], lo);
                        size_t o = (size_t)row * HH + bid * 8 + tig * 2;
                        __stcg((unsigned int*)&g_h_hi[p][o], hi);
                        __stcg((unsigned int*)&g_h_lo[p][o], lo);
                    }
                }
            } else if (t >= 1) {
                #pragma unroll
                for (int nt = 0; nt < 4; ++nt)
                    #pragma unroll
                    for (int qp = 0; qp < 2; ++qp) {
                        int row = rowbase + gid + qp * 8;
                        int gcol = (bid - 128) * 32 + nt * 8 + tig * 2;
                        float2 v = make_float2(acc[nt][qp * 2] + bcol[nt][0],
                                               acc[nt][qp * 2 + 1] + bcol[nt][1]);
                        *(float2*)&y[((size_t)row * TT + (t - 1)) * OUTD + gcol] = v;
                    }
            }
        }

        __syncthreads();        // all pairs' h stores done before arrival
        bar_arrive();           // non-blocking; wait deferred to chunk 2
    }
}

extern "C" void kernel_launch(void* const* d_in, const int* in_sizes, int n_in,
                              void* d_out, int out_size) {
    (void)in_sizes; (void)n_in; (void)out_size;
    cudaFuncSetAttribute(lstm_mma, cudaFuncAttributeMaxDynamicSharedMemorySize, SMEM_TOTAL);
    lstm_mma<<<NCTA, NTHR, SMEM_TOTAL>>>(
        (const float*)d_in[0], (const float*)d_in[1], (const float*)d_in[2],
        (const float*)d_in[3], (const float*)d_in[4], (const float*)d_in[5],
        (const float*)d_in[6], (const float*)d_in[7], (float*)d_out);
}

// round 9
// speedup vs baseline: 1.4938x; 1.4938x over previous
#include <cuda_runtime.h>
#include <cuda_bf16.h>
#include <cstdint>

#define TT 512
#define BATCH 128
#define IND 128
#define HH 1024
#define OUTD 64
#define NCTA 130
#define NTHR 256
#define NCH 18                      // chunks of 64k (4 ksteps)
#define NKS 72

#define OFF_BIAS 0
#define OFF_BFRAG 1024
#define BFRAG_SZ (NKS * 4 * 32 * 16)            // 147456
#define SMEM_TOTAL (OFF_BFRAG + BFRAG_SZ)       // 148480

// A operands pre-packed in mma m16n8k16 fragment order:
// entry [..][mg][s][lane] = uint4(a0,a1,a2,a3); a0=(r,k,k+1) a1=(r+8,·)
// a2=(r,k+8,k+9) a3=(r+8,·), r=16mg+(lane>>2), k=16s+(lane&3)*2.
__device__ uint4 g_uf_hi[(size_t)TT * 8 * 8 * 32];    // [t][mg][s0..7][lane]
__device__ uint4 g_uf_lo[(size_t)TT * 8 * 8 * 32];
__device__ uint4 g_hf_hi[2 * 8 * 64 * 32];            // [ph][mg][hs0..63][lane]
__device__ uint4 g_hf_lo[2 * 8 * 64 * 32];
__device__ unsigned int g_bar_count = 0;
__device__ unsigned int g_bar_gen = 0;

__device__ __forceinline__ float sg(float x) { return __fdividef(1.0f, 1.0f + __expf(-x)); }
__device__ __forceinline__ float th(float x) { return __fdividef(2.0f, 1.0f + __expf(-2.0f * x)) - 1.0f; }

__device__ __forceinline__ uint32_t pkbf(float a, float b, uint32_t& lo) {
    __nv_bfloat16 ah = __float2bfloat16_rn(a), bh = __float2bfloat16_rn(b);
    __nv_bfloat16 al = __float2bfloat16_rn(a - __bfloat162float(ah));
    __nv_bfloat16 bl = __float2bfloat16_rn(b - __bfloat162float(bh));
    lo = (uint32_t)__bfloat16_as_ushort(al) | ((uint32_t)__bfloat16_as_ushort(bl) << 16);
    return (uint32_t)__bfloat16_as_ushort(ah) | ((uint32_t)__bfloat16_as_ushort(bh) << 16);
}

__device__ __forceinline__ void mma_bf16(float* d, const uint32_t* a, uint32_t b0, uint32_t b1) {
    asm volatile(
        "mma.sync.aligned.m16n8k16.row.col.f32.bf16.bf16.f32 "
        "{%0,%1,%2,%3}, {%4,%5,%6,%7}, {%8,%9}, {%0,%1,%2,%3};"
        : "+f"(d[0]), "+f"(d[1]), "+f"(d[2]), "+f"(d[3])
        : "r"(a[0]), "r"(a[1]), "r"(a[2]), "r"(a[3]), "r"(b0), "r"(b1));
}

__device__ __forceinline__ void grid_barrier_full(unsigned int& epoch) {
    __syncthreads();
    if (threadIdx.x == 0) {
        __threadfence();
        unsigned int target = epoch + 1;
        unsigned int arr = atomicAdd(&g_bar_count, 1u);
        if (arr == NCTA - 1) {
            atomicExch(&g_bar_count, 0u);
            __threadfence();
            atomicAdd(&g_bar_gen, 1u);
        } else {
            while ((int)(*(volatile unsigned int*)&g_bar_gen - target) < 0) __nanosleep(32);
        }
        epoch = target;
        __threadfence();
    }
    __syncthreads();
}

__device__ __forceinline__ void bar_arrive() {
    if (threadIdx.x == 0) {
        __threadfence();
        unsigned int arr = atomicAdd(&g_bar_count, 1u);
        if (arr == NCTA - 1) {
            atomicExch(&g_bar_count, 0u);
            __threadfence();
            atomicAdd(&g_bar_gen, 1u);
        }
    }
}
__device__ __forceinline__ void bar_wait(unsigned int target) {
    while ((int)(*(volatile unsigned int*)&g_bar_gen - target) < 0) { }
    __threadfence();
}

// load chunk c's 4 fragment ksteps (hi+lo). tu = u timestep (chunks 0,1);
// hp = h buffer phase (chunks >= 2) — distinct on drain step t=TT.
__device__ __forceinline__ void load_chunk(int tu, int hp, int c, int mg, int lane,
                                           uint4* fh, uint4* fl)
{
    const uint4 *ph, *pl;
    if (c < 2) {
        size_t base = (((size_t)tu * 8 + mg) * 8 + c * 4) * 32 + lane;
        ph = g_uf_hi + base; pl = g_uf_lo + base;
    } else {
        size_t base = (((size_t)hp * 8 + mg) * 64 + (c * 4 - 8)) * 32 + lane;
        ph = g_hf_hi + base; pl = g_hf_lo + base;
    }
    #pragma unroll
    for (int i = 0; i < 4; ++i) {
        fh[i] = __ldcg(ph + i * 32);
        fl[i] = __ldcg(pl + i * 32);
    }
}

__device__ __forceinline__ void compute_chunk(int c, const uint4* fh, const uint4* fl,
                                              float acc[4][4], const char* bf, int lane)
{
    #pragma unroll
    for (int kk = 0; kk < 4; ++kk) {
        const uint32_t* ah = (const uint32_t*)&fh[kk];
        const uint32_t* al = (const uint32_t*)&fl[kk];
        int s = c * 4 + kk;
        #pragma unroll
        for (int nt = 0; nt < 4; ++nt) {
            uint4 bb = *(const uint4*)(bf + (uint32_t)((s * 4 + nt) * 32 + lane) * 16);
            mma_bf16(acc[nt], ah, bb.x, bb.y);   // Ahi * Bhi
            mma_bf16(acc[nt], ah, bb.z, bb.w);   // Ahi * Blo
            mma_bf16(acc[nt], al, bb.x, bb.y);   // Alo * Bhi
        }
    }
}

__global__ void __launch_bounds__(NTHR, 1)
lstm_mma(const float* __restrict__ u, const float* __restrict__ x0,
         const float* __restrict__ kfiz, const float* __restrict__ bfiz,
         const float* __restrict__ kr, const float* __restrict__ br,
         const float* __restrict__ wout, const float* __restrict__ bout,
         float* __restrict__ y)
{
    extern __shared__ char smem[];
    const int tid = threadIdx.x;
    const int bid = blockIdx.x;
    const int mg = tid >> 5, lane = tid & 31;     // 8 warps = 8 row groups
    const int gid = lane >> 2, tig = lane & 3;
    float* bias_s = (float*)(smem + OFF_BIAS);
    unsigned int* base_s = (unsigned int*)(smem + OFF_BIAS + 512);

    // ---- init: weights -> smem B fragments (hi/lo interleaved uint4) ----
    for (int idx = tid; idx < NKS * 4 * 32; idx += NTHR) {
        int l = idx & 31;
        int nt = (idx >> 5) & 3;
        int s = idx >> 7;
        int nloc = nt * 8 + (l >> 2);
        int k0 = s * 16 + (l & 3) * 2;
        float w[4];
        #pragma unroll
        for (int q = 0; q < 4; ++q) {
            int k = k0 + (q >> 1) * 8 + (q & 1);
            float v;
            if (bid < 128) {
                int g = nloc >> 3, hid = bid * 8 + (nloc & 7);
                v = (g < 3) ? kfiz[(size_t)k * 3072 + g * 1024 + hid]
                            : kr[(size_t)k * 1024 + hid];
            } else {
                int col = (bid - 128) * 32 + nloc;
                v = (k < IND) ? 0.0f : wout[(size_t)(k - IND) * OUTD + col];
            }
            w[q] = v;
        }
        uint32_t lo0, lo1;
        uint32_t h0 = pkbf(w[0], w[1], lo0);
        uint32_t h1 = pkbf(w[2], w[3], lo1);
        *(uint4*)(smem + OFF_BFRAG + (uint32_t)idx * 16) = make_uint4(h0, h1, lo0, lo1);
    }
    if (tid < 32) {
        float bv;
        if (bid < 128) {
            int g = tid >> 3, hid = bid * 8 + (tid & 7);
            bv = (g < 3) ? bfiz[g * 1024 + hid] : br[hid];
        } else bv = bout[(bid - 128) * 32 + tid];
        bias_s[tid] = bv;
    }

    // ---- init: u -> fragment layout (grid-strided) ----
    {
        const size_t UN = (size_t)TT * 8 * 8 * 32;
        for (size_t e = (size_t)bid * NTHR + tid; e < UN; e += (size_t)NCTA * NTHR) {
            int el = (int)(e & 31);
            int es = (int)((e >> 5) & 7);
            int emg = (int)((e >> 8) & 7);
            int et = (int)(e >> 11);
            int r = emg * 16 + (el >> 2);
            int k = es * 16 + (el & 3) * 2;
            const float* u0 = u + ((size_t)r * TT + et) * IND + k;
            const float* u8 = u + ((size_t)(r + 8) * TT + et) * IND + k;
            uint32_t l0, l1, l2, l3;
            uint32_t a0 = pkbf(u0[0], u0[1], l0);
            uint32_t a1 = pkbf(u8[0], u8[1], l1);
            uint32_t a2 = pkbf(u0[8], u0[9], l2);
            uint32_t a3 = pkbf(u8[8], u8[9], l3);
            g_uf_hi[e] = make_uint4(a0, a1, a2, a3);
            g_uf_lo[e] = make_uint4(l0, l1, l2, l3);
        }
    }

    // ---- init: c0 (registers), h0 -> fragment layout, phase 0 ----
    const int r0 = mg * 16 + gid, r1 = r0 + 8;
    float creg[4];
    if (bid < 128) {
        creg[0] = x0[(size_t)r0 * 2 * HH + HH + bid * 8 + tig * 2];
        creg[1] = x0[(size_t)r0 * 2 * HH + HH + bid * 8 + tig * 2 + 1];
        creg[2] = x0[(size_t)r1 * 2 * HH + HH + bid * 8 + tig * 2];
        creg[3] = x0[(size_t)r1 * 2 * HH + HH + bid * 8 + tig * 2 + 1];
        float hv0 = x0[(size_t)r0 * 2 * HH + bid * 8 + tig * 2];
        float hv1 = x0[(size_t)r0 * 2 * HH + bid * 8 + tig * 2 + 1];
        float hv2 = x0[(size_t)r1 * 2 * HH + bid * 8 + tig * 2];
        float hv3 = x0[(size_t)r1 * 2 * HH + bid * 8 + tig * 2 + 1];
        uint32_t lo0, lo1;
        uint32_t a0 = pkbf(hv0, hv1, lo0);
        uint32_t a1 = pkbf(hv2, hv3, lo1);
        size_t eo = (((size_t)mg * 64 + (bid >> 1)) * 32 + lane) * 16 + (size_t)(bid & 1) * 8;
        __stcg((uint2*)((char*)g_hf_hi + eo), make_uint2(a0, a1));
        __stcg((uint2*)((char*)g_hf_lo + eo), make_uint2(lo0, lo1));
    }

    unsigned int epoch = 0;
    if (tid == 0) epoch = *(volatile unsigned int*)&g_bar_gen;
    grid_barrier_full(epoch);
    if (tid == 0) *base_s = epoch;
    __syncthreads();
    const unsigned int base = *base_s;

    float bcol[4][2];
    #pragma unroll
    for (int nt = 0; nt < 4; ++nt) {
        bcol[nt][0] = bias_s[nt * 8 + tig * 2];
        bcol[nt][1] = bias_s[nt * 8 + tig * 2 + 1];
    }

    const char* bf = smem + OFF_BFRAG;
    const size_t hstore0 = (((size_t)mg * 64 + (bid >> 1)) * 32 + lane) * 16
                         + (size_t)(bid & 1) * 8;

    uint4 fh0[4], fl0[4], fh1[4], fl1[4];
    load_chunk(0, 0, 0, mg, lane, fh0, fl0);

    for (int t = 0; t <= TT; ++t) {
        const int tt = (t < TT) ? t : (TT - 1);   // u timestep (clamped)
        const int hp = t & 1;                     // h buffer phase (NOT clamped)

        float acc[4][4];
        #pragma unroll
        for (int nt = 0; nt < 4; ++nt)
            #pragma unroll
            for (int q = 0; q < 4; ++q) acc[nt][q] = 0.0f;

        for (int cc = 0; cc < 9; ++cc) {
            const int c0 = 2 * cc, c1 = c0 + 1;
            load_chunk(tt, hp, c1, mg, lane, fh1, fl1);       // c1=1 is u; others h
            compute_chunk(c0, fh0, fl0, acc, bf, lane);
            if (cc < 8) {
                if (cc == 0) bar_wait(base + t);              // h(t) published
                load_chunk(tt, hp, c0 + 2, mg, lane, fh0, fl0);
            } else if (t < TT) {
                int tn = (t + 1 < TT) ? (t + 1) : (TT - 1);
                load_chunk(tn, 0, 0, mg, lane, fh0, fl0);     // next-t u chunk 0
            }
            compute_chunk(c1, fh1, fl1, acc, bf, lane);
        }

        // ---- warp-local epilogue ----
        if (bid < 128) {
            if (t < TT) {
                float hv[4];
                #pragma unroll
                for (int q = 0; q < 4; ++q) {
                    int e = q & 1;
                    float fp = acc[0][q] + bcol[0][e];
                    float ip = acc[1][q] + bcol[1][e];
                    float zp = acc[2][q] + bcol[2][e];
                    float rp = acc[3][q] + bcol[3][e];
                    creg[q] = sg(fp) * creg[q] + sg(ip) * th(rp);
                    hv[q] = sg(zp) * th(creg[q]);
                }
                uint32_t lo0, lo1;
                uint32_t a0 = pkbf(hv[0], hv[1], lo0);
                uint32_t a1 = pkbf(hv[2], hv[3], lo1);
                size_t eo = hstore0 + (size_t)((t + 1) & 1) * (8 * 64 * 32 * 16);
                __stcg((uint2*)((char*)g_hf_hi + eo), make_uint2(a0, a1));
                __stcg((uint2*)((char*)g_hf_lo + eo), make_uint2(lo0, lo1));
            }
        } else if (t >= 1) {
            #pragma unroll
            for (int nt = 0; nt < 4; ++nt) {
                int gcol = (bid - 128) * 32 + nt * 8 + tig * 2;
                float2 v0 = make_float2(acc[nt][0] + bcol[nt][0], acc[nt][1] + bcol[nt][1]);
                float2 v1 = make_float2(acc[nt][2] + bcol[nt][0], acc[nt][3] + bcol[nt][1]);
                *(float2*)&y[((size_t)r0 * TT + (t - 1)) * OUTD + gcol] = v0;
                *(float2*)&y[((size_t)r1 * TT + (t - 1)) * OUTD + gcol] = v1;
            }
        }

        __syncthreads();        // all warps' h stores done before arrival
        bar_arrive();           // non-blocking; wait deferred into next step
    }
}

extern "C" void kernel_launch(void* const* d_in, const int* in_sizes, int n_in,
                              void* d_out, int out_size) {
    (void)in_sizes; (void)n_in; (void)out_size;
    cudaFuncSetAttribute(lstm_mma, cudaFuncAttributeMaxDynamicSharedMemorySize, SMEM_TOTAL);
    lstm_mma<<<NCTA, NTHR, SMEM_TOTAL>>>(
        (const float*)d_in[0], (const float*)d_in[1], (const float*)d_in[2],
        (const float*)d_in[3], (const float*)d_in[4], (const float*)d_in[5],
        (const float*)d_in[6], (const float*)d_in[7], (float*)d_out);
}

// round 10
// speedup vs baseline: 2.1894x; 1.4657x over previous
#include <cuda_runtime.h>
#include <cuda_fp16.h>
#include <cstdint>

#define TT 512
#define BATCH 128
#define IND 128
#define HH 1024
#define OUTD 64
#define NCTA 130
#define NTHR 256
#define NKS 72

#define OFF_BIAS 0
#define OFF_BFRAG 1024
#define BFRAG_SZ (NKS * 2 * 32 * 16)            // 73728 (f16 single, 2 nt per uint4)
#define SMEM_TOTAL (OFF_BFRAG + BFRAG_SZ)       // 74752

// A operands pre-packed in mma m16n8k16 fragment order (f16 hi / f16 lo):
// entry [..][mg][s][lane] = uint4(a0,a1,a2,a3); a0=(r,k,k+1) a1=(r+8,·)
// a2=(r,k+8,k+9) a3=(r+8,·), r=16mg+(lane>>2), k=16s+(lane&3)*2.
__device__ uint4 g_uf_hi[(size_t)TT * 8 * 8 * 32];    // [t][mg][s0..7][lane]
__device__ uint4 g_uf_lo[(size_t)TT * 8 * 8 * 32];
__device__ uint4 g_hf_hi[2 * 8 * 64 * 32];            // [ph][mg][hs0..63][lane]
__device__ uint4 g_hf_lo[2 * 8 * 64 * 32];
__device__ unsigned int g_bar_count = 0;
__device__ unsigned int g_bar_gen = 0;

__device__ __forceinline__ float sg(float x) { return __fdividef(1.0f, 1.0f + __expf(-x)); }
__device__ __forceinline__ float th(float x) { return __fdividef(2.0f, 1.0f + __expf(-2.0f * x)) - 1.0f; }

__device__ __forceinline__ uint32_t pkh(__half a, __half b) {
    return (uint32_t)__half_as_ushort(a) | ((uint32_t)__half_as_ushort(b) << 16);
}
// f16 hi + residual lo pair
__device__ __forceinline__ uint32_t pkf16(float a, float b, uint32_t& lo) {
    __half ah = __float2half_rn(a), bh = __float2half_rn(b);
    __half al = __float2half_rn(a - __half2float(ah));
    __half bl = __float2half_rn(b - __half2float(bh));
    lo = pkh(al, bl);
    return pkh(ah, bh);
}
__device__ __forceinline__ uint32_t pkf16s(float a, float b) {
    return pkh(__float2half_rn(a), __float2half_rn(b));
}

__device__ __forceinline__ void mma_f16(float* d, const uint32_t* a, uint32_t b0, uint32_t b1) {
    asm volatile(
        "mma.sync.aligned.m16n8k16.row.col.f32.f16.f16.f32 "
        "{%0,%1,%2,%3}, {%4,%5,%6,%7}, {%8,%9}, {%0,%1,%2,%3};"
        : "+f"(d[0]), "+f"(d[1]), "+f"(d[2]), "+f"(d[3])
        : "r"(a[0]), "r"(a[1]), "r"(a[2]), "r"(a[3]), "r"(b0), "r"(b1));
}

__device__ __forceinline__ void grid_barrier_full(unsigned int& epoch) {
    __syncthreads();
    if (threadIdx.x == 0) {
        __threadfence();
        unsigned int target = epoch + 1;
        unsigned int arr = atomicAdd(&g_bar_count, 1u);
        if (arr == NCTA - 1) {
            atomicExch(&g_bar_count, 0u);
            __threadfence();
            atomicAdd(&g_bar_gen, 1u);
        } else {
            while ((int)(*(volatile unsigned int*)&g_bar_gen - target) < 0) __nanosleep(32);
        }
        epoch = target;
        __threadfence();
    }
    __syncthreads();
}

__device__ __forceinline__ void bar_arrive() {
    if (threadIdx.x == 0) {
        __threadfence();
        unsigned int arr = atomicAdd(&g_bar_count, 1u);
        if (arr == NCTA - 1) {
            atomicExch(&g_bar_count, 0u);
            __threadfence();
            atomicAdd(&g_bar_gen, 1u);
        }
    }
}
__device__ __forceinline__ void bar_wait(unsigned int target) {
    while ((int)(*(volatile unsigned int*)&g_bar_gen - target) < 0) { }
    __threadfence();
}

// load chunk c's 4 fragment ksteps (hi+lo). tu = u timestep (chunks 0,1);
// hp = h buffer phase (chunks >= 2) — distinct on drain step t=TT.
__device__ __forceinline__ void load_chunk(int tu, int hp, int c, int mg, int lane,
                                           uint4* fh, uint4* fl)
{
    const uint4 *ph, *pl;
    if (c < 2) {
        size_t base = (((size_t)tu * 8 + mg) * 8 + c * 4) * 32 + lane;
        ph = g_uf_hi + base; pl = g_uf_lo + base;
    } else {
        size_t base = (((size_t)hp * 8 + mg) * 64 + (c * 4 - 8)) * 32 + lane;
        ph = g_hf_hi + base; pl = g_hf_lo + base;
    }
    #pragma unroll
    for (int i = 0; i < 4; ++i) {
        fh[i] = __ldcg(ph + i * 32);
        fl[i] = __ldcg(pl + i * 32);
    }
}

// 2-pass f16: Ahi*B + Alo*B; B single f16, 2 nt per uint4
__device__ __forceinline__ void compute_chunk(int c, const uint4* fh, const uint4* fl,
                                              float acc[4][4], const char* bf, int lane)
{
    #pragma unroll
    for (int kk = 0; kk < 4; ++kk) {
        const uint32_t* ah = (const uint32_t*)&fh[kk];
        const uint32_t* al = (const uint32_t*)&fl[kk];
        int s = c * 4 + kk;
        #pragma unroll
        for (int ntp = 0; ntp < 2; ++ntp) {
            uint4 bb = *(const uint4*)(bf + (uint32_t)((s * 2 + ntp) * 32 + lane) * 16);
            mma_f16(acc[2 * ntp + 0], ah, bb.x, bb.y);
            mma_f16(acc[2 * ntp + 0], al, bb.x, bb.y);
            mma_f16(acc[2 * ntp + 1], ah, bb.z, bb.w);
            mma_f16(acc[2 * ntp + 1], al, bb.z, bb.w);
        }
    }
}

__global__ void __launch_bounds__(NTHR, 1)
lstm_mma(const float* __restrict__ u, const float* __restrict__ x0,
         const float* __restrict__ kfiz, const float* __restrict__ bfiz,
         const float* __restrict__ kr, const float* __restrict__ br,
         const float* __restrict__ wout, const float* __restrict__ bout,
         float* __restrict__ y)
{
    extern __shared__ char smem[];
    const int tid = threadIdx.x;
    const int bid = blockIdx.x;
    const int mg = tid >> 5, lane = tid & 31;     // 8 warps = 8 row groups
    const int gid = lane >> 2, tig = lane & 3;
    float* bias_s = (float*)(smem + OFF_BIAS);
    unsigned int* base_s = (unsigned int*)(smem + OFF_BIAS + 512);

    // ---- init: weights -> smem B fragments (f16 single, 2 nt per uint4) ----
    for (int idx = tid; idx < NKS * 2 * 32; idx += NTHR) {
        int l = idx & 31;
        int ntp = (idx >> 5) & 1;
        int s = idx >> 6;
        uint32_t r[4];
        #pragma unroll
        for (int half = 0; half < 2; ++half) {
            int nt = ntp * 2 + half;
            int nloc = nt * 8 + (l >> 2);
            int k0 = s * 16 + (l & 3) * 2;
            float w[4];
            #pragma unroll
            for (int q = 0; q < 4; ++q) {
                int k = k0 + (q >> 1) * 8 + (q & 1);
                float v;
                if (bid < 128) {
                    int g = nloc >> 3, hid = bid * 8 + (nloc & 7);
                    v = (g < 3) ? kfiz[(size_t)k * 3072 + g * 1024 + hid]
                                : kr[(size_t)k * 1024 + hid];
                } else {
                    int col = (bid - 128) * 32 + nloc;
                    v = (k < IND) ? 0.0f : wout[(size_t)(k - IND) * OUTD + col];
                }
                w[q] = v;
            }
            r[half * 2 + 0] = pkf16s(w[0], w[1]);
            r[half * 2 + 1] = pkf16s(w[2], w[3]);
        }
        *(uint4*)(smem + OFF_BFRAG + (uint32_t)idx * 16) = make_uint4(r[0], r[1], r[2], r[3]);
    }
    if (tid < 32) {
        float bv;
        if (bid < 128) {
            int g = tid >> 3, hid = bid * 8 + (tid & 7);
            bv = (g < 3) ? bfiz[g * 1024 + hid] : br[hid];
        } else bv = bout[(bid - 128) * 32 + tid];
        bias_s[tid] = bv;
    }

    // ---- init: u -> fragment layout (f16 hi/lo, grid-strided) ----
    {
        const size_t UN = (size_t)TT * 8 * 8 * 32;
        for (size_t e = (size_t)bid * NTHR + tid; e < UN; e += (size_t)NCTA * NTHR) {
            int el = (int)(e & 31);
            int es = (int)((e >> 5) & 7);
            int emg = (int)((e >> 8) & 7);
            int et = (int)(e >> 11);
            int r = emg * 16 + (el >> 2);
            int k = es * 16 + (el & 3) * 2;
            const float* u0 = u + ((size_t)r * TT + et) * IND + k;
            const float* u8 = u + ((size_t)(r + 8) * TT + et) * IND + k;
            uint32_t l0, l1, l2, l3;
            uint32_t a0 = pkf16(u0[0], u0[1], l0);
            uint32_t a1 = pkf16(u8[0], u8[1], l1);
            uint32_t a2 = pkf16(u0[8], u0[9], l2);
            uint32_t a3 = pkf16(u8[8], u8[9], l3);
            g_uf_hi[e] = make_uint4(a0, a1, a2, a3);
            g_uf_lo[e] = make_uint4(l0, l1, l2, l3);
        }
    }

    // ---- init: c0 (registers), h0 -> fragment layout, phase 0 ----
    const int r0 = mg * 16 + gid, r1 = r0 + 8;
    float creg[4];
    if (bid < 128) {
        creg[0] = x0[(size_t)r0 * 2 * HH + HH + bid * 8 + tig * 2];
        creg[1] = x0[(size_t)r0 * 2 * HH + HH + bid * 8 + tig * 2 + 1];
        creg[2] = x0[(size_t)r1 * 2 * HH + HH + bid * 8 + tig * 2];
        creg[3] = x0[(size_t)r1 * 2 * HH + HH + bid * 8 + tig * 2 + 1];
        float hv0 = x0[(size_t)r0 * 2 * HH + bid * 8 + tig * 2];
        float hv1 = x0[(size_t)r0 * 2 * HH + bid * 8 + tig * 2 + 1];
        float hv2 = x0[(size_t)r1 * 2 * HH + bid * 8 + tig * 2];
        float hv3 = x0[(size_t)r1 * 2 * HH + bid * 8 + tig * 2 + 1];
        uint32_t lo0, lo1;
        uint32_t a0 = pkf16(hv0, hv1, lo0);
        uint32_t a1 = pkf16(hv2, hv3, lo1);
        size_t eo = (((size_t)mg * 64 + (bid >> 1)) * 32 + lane) * 16 + (size_t)(bid & 1) * 8;
        __stcg((uint2*)((char*)g_hf_hi + eo), make_uint2(a0, a1));
        __stcg((uint2*)((char*)g_hf_lo + eo), make_uint2(lo0, lo1));
    }

    unsigned int epoch = 0;
    if (tid == 0) epoch = *(volatile unsigned int*)&g_bar_gen;
    grid_barrier_full(epoch);
    if (tid == 0) *base_s = epoch;
    __syncthreads();
    const unsigned int base = *base_s;

    float bcol[4][2];
    #pragma unroll
    for (int nt = 0; nt < 4; ++nt) {
        bcol[nt][0] = bias_s[nt * 8 + tig * 2];
        bcol[nt][1] = bias_s[nt * 8 + tig * 2 + 1];
    }

    const char* bf = smem + OFF_BFRAG;
    const size_t hstore0 = (((size_t)mg * 64 + (bid >> 1)) * 32 + lane) * 16
                         + (size_t)(bid & 1) * 8;

    // depth-3 register staging: chunk c lives in buffer c%3
    uint4 fh[3][4], fl[3][4];
    load_chunk(0, 0, 0, mg, lane, fh[0], fl[0]);
    load_chunk(0, 0, 1, mg, lane, fh[1], fl[1]);

    for (int t = 0; t <= TT; ++t) {
        const int tt = (t < TT) ? t : (TT - 1);   // u timestep (clamped)
        const int hp = t & 1;                     // h buffer phase (NOT clamped)

        float acc[4][4];
        #pragma unroll
        for (int nt = 0; nt < 4; ++nt)
            #pragma unroll
            for (int q = 0; q < 4; ++q) acc[nt][q] = 0.0f;

        compute_chunk(0, fh[0], fl[0], acc, bf, lane);
        bar_wait(base + t);                       // h(t) published
        load_chunk(tt, hp, 2, mg, lane, fh[2], fl[2]);

        #pragma unroll
        for (int c = 1; c < 18; ++c) {
            if (c <= 15) {
                load_chunk(tt, hp, c + 2, mg, lane, fh[(c + 2) % 3], fl[(c + 2) % 3]);
            } else if (t < TT) {
                int tn = (t + 1 < TT) ? (t + 1) : (TT - 1);
                load_chunk(tn, 0, c - 16, mg, lane, fh[(c + 2) % 3], fl[(c + 2) % 3]);
            }
            compute_chunk(c, fh[c % 3], fl[c % 3], acc, bf, lane);
        }

        // ---- warp-local epilogue ----
        if (bid < 128) {
            if (t < TT) {
                float hv[4];
                #pragma unroll
                for (int q = 0; q < 4; ++q) {
                    int e = q & 1;
                    float fp = acc[0][q] + bcol[0][e];
                    float ip = acc[1][q] + bcol[1][e];
                    float zp = acc[2][q] + bcol[2][e];
                    float rp = acc[3][q] + bcol[3][e];
                    creg[q] = sg(fp) * creg[q] + sg(ip) * th(rp);
                    hv[q] = sg(zp) * th(creg[q]);
                }
                uint32_t lo0, lo1;
                uint32_t a0 = pkf16(hv[0], hv[1], lo0);
                uint32_t a1 = pkf16(hv[2], hv[3], lo1);
                size_t eo = hstore0 + (size_t)((t + 1) & 1) * (8 * 64 * 32 * 16);
                __stcg((uint2*)((char*)g_hf_hi + eo), make_uint2(a0, a1));
                __stcg((uint2*)((char*)g_hf_lo + eo), make_uint2(lo0, lo1));
            }
        } else if (t >= 1) {
            #pragma unroll
            for (int nt = 0; nt < 4; ++nt) {
                int gcol = (bid - 128) * 32 + nt * 8 + tig * 2;
                float2 v0 = make_float2(acc[nt][0] + bcol[nt][0], acc[nt][1] + bcol[nt][1]);
                float2 v1 = make_float2(acc[nt][2] + bcol[nt][0], acc[nt][3] + bcol[nt][1]);
                *(float2*)&y[((size_t)r0 * TT + (t - 1)) * OUTD + gcol] = v0;
                *(float2*)&y[((size_t)r1 * TT + (t - 1)) * OUTD + gcol] = v1;
            }
        }

        __syncthreads();        // all warps' h stores done before arrival
        bar_arrive();           // non-blocking; wait deferred into next step
    }
}

extern "C" void kernel_launch(void* const* d_in, const int* in_sizes, int n_in,
                              void* d_out, int out_size) {
    (void)in_sizes; (void)n_in; (void)out_size;
    cudaFuncSetAttribute(lstm_mma, cudaFuncAttributeMaxDynamicSharedMemorySize, SMEM_TOTAL);
    lstm_mma<<<NCTA, NTHR, SMEM_TOTAL>>>(
        (const float*)d_in[0], (const float*)d_in[1], (const float*)d_in[2],
        (const float*)d_in[3], (const float*)d_in[4], (const float*)d_in[5],
        (const float*)d_in[6], (const float*)d_in[7], (float*)d_out);
}

// round 13
// speedup vs baseline: 2.7009x; 1.2336x over previous
#include <cuda_runtime.h>
#include <cuda_fp16.h>
#include <cstdint>

#define TT 512
#define BATCH 128
#define IND 128
#define HH 1024
#define OUTD 64
#define NCTA 130
#define NTHR 256
#define NKS 72

#define OFF_BIAS 0
#define OFF_BFRAG 1024
#define BFRAG_SZ (NKS * 2 * 32 * 16)            // 73728 (f16, 2 nt per uint4)
#define SMEM_TOTAL (OFF_BFRAG + BFRAG_SZ)       // 74752

// A operands pre-packed in mma m16n8k16 fragment order, SINGLE f16:
// entry [..][mg][s][lane] = uint4(a0,a1,a2,a3); a0=(r,k,k+1) a1=(r+8,·)
// a2=(r,k+8,k+9) a3=(r+8,·), r=16mg+(lane>>2), k=16s+(lane&3)*2.
__device__ uint4 g_uf[(size_t)TT * 8 * 8 * 32];       // [t][mg][s0..7][lane]
__device__ uint4 g_hf[2 * 8 * 64 * 32];               // [ph][mg][hs0..63][lane]
__device__ unsigned int g_bar_count = 0;
__device__ unsigned int g_bar_gen = 0;

__device__ __forceinline__ float sg(float x) { return __fdividef(1.0f, 1.0f + __expf(-x)); }
__device__ __forceinline__ float th(float x) { return __fdividef(2.0f, 1.0f + __expf(-2.0f * x)) - 1.0f; }

__device__ __forceinline__ uint32_t pkf16s(float a, float b) {
    return (uint32_t)__half_as_ushort(__float2half_rn(a))
         | ((uint32_t)__half_as_ushort(__float2half_rn(b)) << 16);
}

__device__ __forceinline__ void mma_f16(float* d, const uint32_t* a, uint32_t b0, uint32_t b1) {
    asm volatile(
        "mma.sync.aligned.m16n8k16.row.col.f32.f16.f16.f32 "
        "{%0,%1,%2,%3}, {%4,%5,%6,%7}, {%8,%9}, {%0,%1,%2,%3};"
        : "+f"(d[0]), "+f"(d[1]), "+f"(d[2]), "+f"(d[3])
        : "r"(a[0]), "r"(a[1]), "r"(a[2]), "r"(a[3]), "r"(b0), "r"(b1));
}

__device__ __forceinline__ void grid_barrier_full(unsigned int& epoch) {
    __syncthreads();
    if (threadIdx.x == 0) {
        __threadfence();
        unsigned int target = epoch + 1;
        unsigned int arr = atomicAdd(&g_bar_count, 1u);
        if (arr == NCTA - 1) {
            atomicExch(&g_bar_count, 0u);
            __threadfence();
            atomicAdd(&g_bar_gen, 1u);
        } else {
            while ((int)(*(volatile unsigned int*)&g_bar_gen - target) < 0) __nanosleep(32);
        }
        epoch = target;
        __threadfence();
    }
    __syncthreads();
}

__device__ __forceinline__ void bar_arrive() {
    if (threadIdx.x == 0) {
        __threadfence();
        unsigned int arr = atomicAdd(&g_bar_count, 1u);
        if (arr == NCTA - 1) {
            atomicExch(&g_bar_count, 0u);
            __threadfence();
            atomicAdd(&g_bar_gen, 1u);
        }
    }
}
__device__ __forceinline__ void bar_wait(unsigned int target) {
    while ((int)(*(volatile unsigned int*)&g_bar_gen - target) < 0) { }
    __threadfence();
}

// load chunk c's 4 fragment ksteps. tu = u timestep (chunks 0,1);
// hp = h buffer phase (chunks >= 2) — distinct on drain step t=TT.
__device__ __forceinline__ void load_chunk(int tu, int hp, int c, int mg, int lane,
                                           uint4* fh)
{
    const uint4* ph;
    if (c < 2) {
        ph = g_uf + (((size_t)tu * 8 + mg) * 8 + c * 4) * 32 + lane;
    } else {
        ph = g_hf + (((size_t)hp * 8 + mg) * 64 + (c * 4 - 8)) * 32 + lane;
    }
    #pragma unroll
    for (int i = 0; i < 4; ++i) fh[i] = __ldcg(ph + i * 32);
}

// 1-pass f16: A*B; B f16, 2 nt per uint4
__device__ __forceinline__ void compute_chunk(int c, const uint4* fh,
                                              float acc[4][4], const char* bf, int lane)
{
    #pragma unroll
    for (int kk = 0; kk < 4; ++kk) {
        const uint32_t* a = (const uint32_t*)&fh[kk];
        int s = c * 4 + kk;
        #pragma unroll
        for (int ntp = 0; ntp < 2; ++ntp) {
            uint4 bb = *(const uint4*)(bf + (uint32_t)((s * 2 + ntp) * 32 + lane) * 16);
            mma_f16(acc[2 * ntp + 0], a, bb.x, bb.y);
            mma_f16(acc[2 * ntp + 1], a, bb.z, bb.w);
        }
    }
}

__global__ void __launch_bounds__(NTHR, 1)
lstm_mma(const float* __restrict__ u, const float* __restrict__ x0,
         const float* __restrict__ kfiz, const float* __restrict__ bfiz,
         const float* __restrict__ kr, const float* __restrict__ br,
         const float* __restrict__ wout, const float* __restrict__ bout,
         float* __restrict__ y)
{
    extern __shared__ char smem[];
    const int tid = threadIdx.x;
    const int bid = blockIdx.x;
    const int mg = tid >> 5, lane = tid & 31;     // 8 warps = 8 row groups
    const int gid = lane >> 2, tig = lane & 3;
    float* bias_s = (float*)(smem + OFF_BIAS);
    unsigned int* base_s = (unsigned int*)(smem + OFF_BIAS + 512);

    // ---- init: weights -> smem B fragments (f16, 2 nt per uint4) ----
    for (int idx = tid; idx < NKS * 2 * 32; idx += NTHR) {
        int l = idx & 31;
        int ntp = (idx >> 5) & 1;
        int s = idx >> 6;
        uint32_t r[4];
        #pragma unroll
        for (int half = 0; half < 2; ++half) {
            int nt = ntp * 2 + half;
            int nloc = nt * 8 + (l >> 2);
            int k0 = s * 16 + (l & 3) * 2;
            float w[4];
            #pragma unroll
            for (int q = 0; q < 4; ++q) {
                int k = k0 + (q >> 1) * 8 + (q & 1);
                float v;
                if (bid < 128) {
                    int g = nloc >> 3, hid = bid * 8 + (nloc & 7);
                    v = (g < 3) ? kfiz[(size_t)k * 3072 + g * 1024 + hid]
                                : kr[(size_t)k * 1024 + hid];
                } else {
                    int col = (bid - 128) * 32 + nloc;
                    v = (k < IND) ? 0.0f : wout[(size_t)(k - IND) * OUTD + col];
                }
                w[q] = v;
            }
            r[half * 2 + 0] = pkf16s(w[0], w[1]);
            r[half * 2 + 1] = pkf16s(w[2], w[3]);
        }
        *(uint4*)(smem + OFF_BFRAG + (uint32_t)idx * 16) = make_uint4(r[0], r[1], r[2], r[3]);
    }
    if (tid < 32) {
        float bv;
        if (bid < 128) {
            int g = tid >> 3, hid = bid * 8 + (tid & 7);
            bv = (g < 3) ? bfiz[g * 1024 + hid] : br[hid];
        } else bv = bout[(bid - 128) * 32 + tid];
        bias_s[tid] = bv;
    }

    // ---- init: u -> fragment layout (single f16, grid-strided) ----
    {
        const size_t UN = (size_t)TT * 8 * 8 * 32;
        for (size_t e = (size_t)bid * NTHR + tid; e < UN; e += (size_t)NCTA * NTHR) {
            int el = (int)(e & 31);
            int es = (int)((e >> 5) & 7);
            int emg = (int)((e >> 8) & 7);
            int et = (int)(e >> 11);
            int r = emg * 16 + (el >> 2);
            int k = es * 16 + (el & 3) * 2;
            const float* u0 = u + ((size_t)r * TT + et) * IND + k;
            const float* u8 = u + ((size_t)(r + 8) * TT + et) * IND + k;
            g_uf[e] = make_uint4(pkf16s(u0[0], u0[1]), pkf16s(u8[0], u8[1]),
                                 pkf16s(u0[8], u0[9]), pkf16s(u8[8], u8[9]));
        }
    }

    // ---- init: c0 (registers), h0 -> fragment layout, phase 0 ----
    const int r0 = mg * 16 + gid, r1 = r0 + 8;
    float creg[4];
    if (bid < 128) {
        creg[0] = x0[(size_t)r0 * 2 * HH + HH + bid * 8 + tig * 2];
        creg[1] = x0[(size_t)r0 * 2 * HH + HH + bid * 8 + tig * 2 + 1];
        creg[2] = x0[(size_t)r1 * 2 * HH + HH + bid * 8 + tig * 2];
        creg[3] = x0[(size_t)r1 * 2 * HH + HH + bid * 8 + tig * 2 + 1];
        float hv0 = x0[(size_t)r0 * 2 * HH + bid * 8 + tig * 2];
        float hv1 = x0[(size_t)r0 * 2 * HH + bid * 8 + tig * 2 + 1];
        float hv2 = x0[(size_t)r1 * 2 * HH + bid * 8 + tig * 2];
        float hv3 = x0[(size_t)r1 * 2 * HH + bid * 8 + tig * 2 + 1];
        size_t eo = (((size_t)mg * 64 + (bid >> 1)) * 32 + lane) * 16 + (size_t)(bid & 1) * 8;
        __stcg((uint2*)((char*)g_hf + eo), make_uint2(pkf16s(hv0, hv1), pkf16s(hv2, hv3)));
    }

    unsigned int epoch = 0;
    if (tid == 0) epoch = *(volatile unsigned int*)&g_bar_gen;
    grid_barrier_full(epoch);
    if (tid == 0) *base_s = epoch;
    __syncthreads();
    const unsigned int base = *base_s;

    float bcol[4][2];
    #pragma unroll
    for (int nt = 0; nt < 4; ++nt) {
        bcol[nt][0] = bias_s[nt * 8 + tig * 2];
        bcol[nt][1] = bias_s[nt * 8 + tig * 2 + 1];
    }

    const char* bf = smem + OFF_BFRAG;
    const size_t hstore0 = (((size_t)mg * 64 + (bid >> 1)) * 32 + lane) * 16
                         + (size_t)(bid & 1) * 8;

    // depth-3 register staging: chunk c lives in buffer c%3 (18%3==0 ->
    // ring position is step-invariant, so next-step tail prefetch lands
    // in the right buffers)
    uint4 fh[3][4];
    load_chunk(0, 0, 0, mg, lane, fh[0]);
    load_chunk(0, 0, 1, mg, lane, fh[1]);

    for (int t = 0; t <= TT; ++t) {
        const int tt = (t < TT) ? t : (TT - 1);   // u timestep (clamped)
        const int hp = t & 1;                     // h buffer phase (NOT clamped)

        float acc[4][4];
        #pragma unroll
        for (int nt = 0; nt < 4; ++nt)
            #pragma unroll
            for (int q = 0; q < 4; ++q) acc[nt][q] = 0.0f;

        compute_chunk(0, fh[0], acc, bf, lane);
        bar_wait(base + t);                       // h(t) published
        load_chunk(tt, hp, 2, mg, lane, fh[2]);

        #pragma unroll
        for (int c = 1; c < 18; ++c) {
            if (c <= 15) {
                load_chunk(tt, hp, c + 2, mg, lane, fh[(c + 2) % 3]);
            } else if (t < TT) {
                int tn = (t + 1 < TT) ? (t + 1) : (TT - 1);
                load_chunk(tn, 0, c - 16, mg, lane, fh[(c + 2) % 3]);
            }
            compute_chunk(c, fh[c % 3], acc, bf, lane);
        }

        // ---- warp-local epilogue ----
        if (bid < 128) {
            if (t < TT) {
                float hv[4];
                #pragma unroll
                for (int q = 0; q < 4; ++q) {
                    int e = q & 1;
                    float fp = acc[0][q] + bcol[0][e];
                    float ip = acc[1][q] + bcol[1][e];
                    float zp = acc[2][q] + bcol[2][e];
                    float rp = acc[3][q] + bcol[3][e];
                    creg[q] = sg(fp) * creg[q] + sg(ip) * th(rp);
                    hv[q] = sg(zp) * th(creg[q]);
                }
                size_t eo = hstore0 + (size_t)((t + 1) & 1) * (8 * 64 * 32 * 16);
                __stcg((uint2*)((char*)g_hf + eo),
                       make_uint2(pkf16s(hv[0], hv[1]), pkf16s(hv[2], hv[3])));
            }
        } else if (t >= 1) {
            #pragma unroll
            for (int nt = 0; nt < 4; ++nt) {
                int gcol = (bid - 128) * 32 + nt * 8 + tig * 2;
                float2 v0 = make_float2(acc[nt][0] + bcol[nt][0], acc[nt][1] + bcol[nt][1]);
                float2 v1 = make_float2(acc[nt][2] + bcol[nt][0], acc[nt][3] + bcol[nt][1]);
                *(float2*)&y[((size_t)r0 * TT + (t - 1)) * OUTD + gcol] = v0;
                *(float2*)&y[((size_t)r1 * TT + (t - 1)) * OUTD + gcol] = v1;
            }
        }

        __syncthreads();        // all warps' h stores done before arrival
        bar_arrive();           // non-blocking; wait deferred into next step
    }
}

extern "C" void kernel_launch(void* const* d_in, const int* in_sizes, int n_in,
                              void* d_out, int out_size) {
    (void)in_sizes; (void)n_in; (void)out_size;
    cudaFuncSetAttribute(lstm_mma, cudaFuncAttributeMaxDynamicSharedMemorySize, SMEM_TOTAL);
    lstm_mma<<<NCTA, NTHR, SMEM_TOTAL>>>(
        (const float*)d_in[0], (const float*)d_in[1], (const float*)d_in[2],
        (const float*)d_in[3], (const float*)d_in[4], (const float*)d_in[5],
        (const float*)d_in[6], (const float*)d_in[7], (float*)d_out);
}